// round 16
// baseline (speedup 1.0000x reference)
#include <cuda_runtime.h>
#include <cuda_bf16.h>
#include <cstdint>

#define BATCH    4096
#define MTILE    16
#define NBLOCKS  (BATCH / MTILE)   // 256
#define NTHREADS 256               // 8 warps = 8 n-chunks
#define FRAG_PER_BLOCK 28          // 7168 fragment-entries / 256 blocks

// B fragments pre-laid-out for HMMA: index f=((nc*4+ks)*7+nt), lane gets
// uint4 {bh0, bh1, bl0, bl1} at g_bfrag[f*32 + lane]. 114688 B, L2-resident.
__device__ __align__(16) uint4 g_bfrag[4 * 56 * 32];
__device__ int g_prod = 0;   // blocks that published their fragment slice
__device__ int g_done = 0;   // blocks finished (for counter reset)

// smem byte offsets
#define OFF_AH   0                          // 16 x 128 B
#define OFF_AL   2048
#define OFF_P    4096                       // 64 x stride17 f32
#define OFF_XP   (OFF_P + 64 * 17 * 4)      // 7 x stride17 f32
#define OFF_RD   (OFF_XP + 7 * 17 * 4)      // 16 f32
#define OFF_RED  (OFF_RD + 64)              // 8 warps x 16 rows f32
#define OFF_MSM  (OFF_RED + 8 * 16 * 4)     // 24 x 16 f32
#define OFF_SS   (OFF_MSM + 24 * 16 * 4)    // 6 x 16 f32
#define SMEM_BYTES (OFF_SS + 6 * 16 * 4 + 16)

static __device__ __forceinline__ uint32_t packbf2(__nv_bfloat16 lo, __nv_bfloat16 hi) {
    __nv_bfloat162 t(lo, hi);
    return *reinterpret_cast<uint32_t*>(&t);
}
static __device__ __forceinline__ void bsplit(float v, __nv_bfloat16& h, __nv_bfloat16& l) {
    h = __float2bfloat16(v);
    l = __float2bfloat16(v - __bfloat162float(h));
}
static __device__ __forceinline__ void mma16816(float* d, const uint32_t* a,
                                                uint32_t b0, uint32_t b1) {
    asm("mma.sync.aligned.m16n8k16.row.col.f32.bf16.bf16.f32 "
        "{%0,%1,%2,%3}, {%4,%5,%6,%7}, {%8,%9}, {%0,%1,%2,%3};"
        : "+f"(d[0]), "+f"(d[1]), "+f"(d[2]), "+f"(d[3])
        : "r"(a[0]), "r"(a[1]), "r"(a[2]), "r"(a[3]), "r"(b0), "r"(b1));
}
// L2-coherent 128-bit load (g_bfrag is produced DURING this kernel; the
// nc/__ldg path is only safe for launch-constant data).
static __device__ __forceinline__ uint4 ldgcg(const uint4* p) {
    uint4 v;
    asm volatile("ld.global.cg.v4.u32 {%0,%1,%2,%3}, [%4];"
                 : "=r"(v.x), "=r"(v.y), "=r"(v.z), "=r"(v.w)
                 : "l"(__cvta_generic_to_global(p)));
    return v;
}

__global__ void __launch_bounds__(NTHREADS, 2) anfis_fused_kernel(
    const float* __restrict__ x, const float* __restrict__ a,
    const float* __restrict__ b, const float* __restrict__ c,
    const float* __restrict__ coeff, float* __restrict__ out)
{
    extern __shared__ char smem[];
    float* Ps  = reinterpret_cast<float*>(smem + OFF_P);
    float* Xs  = reinterpret_cast<float*>(smem + OFF_XP);
    float* Rd  = reinterpret_cast<float*>(smem + OFF_RD);
    float* Msm = reinterpret_cast<float*>(smem + OFF_MSM);  // [(i*4+k)*16 + bl]
    float* Ss  = reinterpret_cast<float*>(smem + OFF_SS);   // [i*16 + bl]

    const int tid  = threadIdx.x;
    const int lane = tid & 31;
    const int wid  = tid >> 5;
    const int bid  = blockIdx.x;
    const int b0   = bid * MTILE;

    // ---- Producer slice (warp 7, lanes 0..27): 28 fragment-entries/block ----
    // Runs concurrently with phase A (warps 0-2). Uniform cost across blocks.
    if (wid == 7) {
        if (lane < FRAG_PER_BLOCK) {
            const int e   = bid * FRAG_PER_BLOCK + lane;   // 0..7167
            const int el  = e & 31;
            const int f   = e >> 5;
            const int nt  = f % 7;
            const int t2  = f / 7;
            const int ks  = t2 & 3;
            const int nc  = t2 >> 2;
            const int n   = nc * 56 + nt * 8 + (el >> 2);
            const int h   = n / 7;
            const int j   = n - h * 7;
            const int k0  = ks * 16 + 2 * (el & 3);

            float v0 = __ldg(&coeff[(h * 64 + k0) * 7 + j]);
            float v1 = __ldg(&coeff[(h * 64 + k0 + 1) * 7 + j]);
            float v2 = __ldg(&coeff[(h * 64 + k0 + 8) * 7 + j]);
            float v3 = __ldg(&coeff[(h * 64 + k0 + 9) * 7 + j]);

            __nv_bfloat16 h0, l0, h1, l1, h2, l2, h3, l3;
            bsplit(v0, h0, l0);
            bsplit(v1, h1, l1);
            bsplit(v2, h2, l2);
            bsplit(v3, h3, l3);

            uint4 o;
            o.x = packbf2(h0, h1);
            o.y = packbf2(h2, h3);
            o.z = packbf2(l0, l1);
            o.w = packbf2(l2, l3);
            g_bfrag[f * 32 + el] = o;
        }
        __syncwarp();
        if (lane == 0) {
            __threadfence();        // publish stores before signaling
            atomicAdd(&g_prod, 1);
        }
    }

    // ---- Phase A: memberships, (b,i) task per thread (96 threads) ----
    if (tid < 96) {
        const int bl = tid & 15;
        const int i  = tid >> 4;       // 0..5
        float xi = __ldg(&x[(b0 + bl) * 6 + i]);
        Xs[i * 17 + bl] = xi;
        float s = 0.0f;
        #pragma unroll
        for (int k = 0; k < 4; k++) {
            float av = __ldg(&a[i * 4 + k]);
            float bv = __ldg(&b[i * 4 + k]);
            float cv = __ldg(&c[i * 4 + k]);
            float d  = __fdividef(xi - cv, av);
            float d2 = d * d;
            float db = (bv == 2.0f) ? (d2 * d2) : __powf(d2, bv);
            float mv = __fdividef(1.0f, 1.0f + db);
            Msm[(i * 4 + k) * 16 + bl] = mv;
            s += mv;
        }
        Ss[i * 16 + bl] = s;
    }
    __syncthreads();

    // ---- Phase B: den, P table, A tiles — all 256 threads ----
    if (tid < 16) {
        float den = Ss[tid] * Ss[16 + tid] * Ss[32 + tid]
                  * Ss[48 + tid] * Ss[64 + tid] * Ss[80 + tid];
        Rd[tid] = __fdividef(1.0f, fmaxf(den, 1e-12f));
        Xs[6 * 17 + tid] = 1.0f;
    }
    #pragma unroll
    for (int q = 0; q < 4; q++) {
        const int e  = tid + q * 256;
        const int h  = e >> 4;
        const int bl = e & 15;
        Ps[h * 17 + bl] = Msm[(0 + ((h >> 4) & 3)) * 16 + bl]
                        * Msm[(4 + ((h >> 2) & 3)) * 16 + bl]
                        * Msm[(8 + (h & 3)) * 16 + bl];
    }
    #pragma unroll
    for (int q = 0; q < 2; q++) {
        const int u  = tid + q * 256;
        const int bl = u & 15;
        const int l  = (u >> 4) * 2;   // even l
        float tt = Msm[(12 + ((l >> 4) & 3)) * 16 + bl]
                 * Msm[(16 + ((l >> 2) & 3)) * 16 + bl];
        float q0 = tt * Msm[(20 + (l & 3)) * 16 + bl];
        float q1 = tt * Msm[(20 + ((l & 3) + 1)) * 16 + bl];
        __nv_bfloat16 h0, l0, h1, l1;
        bsplit(q0, h0, l0);
        bsplit(q1, h1, l1);
        uint32_t cb = (uint32_t)(l * 2) ^ (uint32_t)((bl & 7) << 4);
        *reinterpret_cast<uint32_t*>(smem + OFF_AH + bl * 128 + cb) = packbf2(h0, h1);
        *reinterpret_cast<uint32_t*>(smem + OFF_AL + bl * 128 + cb) = packbf2(l0, l1);
    }

    // ---- Grid barrier: wait for all 256 fragment slices (volatile poll) ----
    if (tid == 0) {
        const volatile int* gp = &g_prod;
        while (*gp < NBLOCKS) {}
        __threadfence();
    }
    __syncthreads();   // exec + memory barrier: no consumer load hoists above

    // ---- HMMA mainloop: warp = 56-col chunk; double-buffered B via L2 (.cg) ----
    const int nc = wid;

    float acc[7][4];
    #pragma unroll
    for (int nt = 0; nt < 7; nt++)
        #pragma unroll
        for (int e = 0; e < 4; e++) acc[nt][e] = 0.0f;

    const int r  = lane >> 2;
    const int c4 = (lane & 3) * 4;
    const uint32_t rsw = (uint32_t)(r << 4);

    uint4 bf[2][7];
    #pragma unroll
    for (int nt = 0; nt < 7; nt++)
        bf[0][nt] = ldgcg(&g_bfrag[(((nc * 4 + 0) * 7 + nt) * 32) + lane]);

    #pragma unroll
    for (int ks = 0; ks < 4; ks++) {
        const int cur = ks & 1;
        if (ks < 3) {
            #pragma unroll
            for (int nt = 0; nt < 7; nt++)
                bf[cur ^ 1][nt] =
                    ldgcg(&g_bfrag[(((nc * 4 + ks + 1) * 7 + nt) * 32) + lane]);
        }
        const uint32_t cb0 = (uint32_t)(ks * 32 + c4) ^ rsw;
        const uint32_t cb1 = (uint32_t)(ks * 32 + c4 + 16) ^ rsw;
        uint32_t ah[4], al[4];
        {
            ah[0] = *reinterpret_cast<const uint32_t*>(smem + OFF_AH + r * 128 + cb0);
            ah[1] = *reinterpret_cast<const uint32_t*>(smem + OFF_AH + (r + 8) * 128 + cb0);
            ah[2] = *reinterpret_cast<const uint32_t*>(smem + OFF_AH + r * 128 + cb1);
            ah[3] = *reinterpret_cast<const uint32_t*>(smem + OFF_AH + (r + 8) * 128 + cb1);
            al[0] = *reinterpret_cast<const uint32_t*>(smem + OFF_AL + r * 128 + cb0);
            al[1] = *reinterpret_cast<const uint32_t*>(smem + OFF_AL + (r + 8) * 128 + cb0);
            al[2] = *reinterpret_cast<const uint32_t*>(smem + OFF_AL + r * 128 + cb1);
            al[3] = *reinterpret_cast<const uint32_t*>(smem + OFF_AL + (r + 8) * 128 + cb1);
        }
        #pragma unroll
        for (int nt = 0; nt < 7; nt++) {
            mma16816(acc[nt], ah, bf[cur][nt].x, bf[cur][nt].y);   // hi*hi
            mma16816(acc[nt], ah, bf[cur][nt].z, bf[cur][nt].w);   // hi*lo
            mma16816(acc[nt], al, bf[cur][nt].x, bf[cur][nt].y);   // lo*hi
        }
    }

    // ---- Epilogue: fold P * x_plus, reduce quads, stash per-warp rows ----
    {
        float rsum[2] = {0.f, 0.f};
        #pragma unroll
        for (int nt = 0; nt < 7; nt++)
            #pragma unroll
            for (int e = 0; e < 4; e++) {
                const int row = r + (e >> 1) * 8;     // 0..15
                const int u   = nt * 8 + 2 * (lane & 3) + (e & 1);
                const int h   = u / 7;
                const int j   = u - h * 7;
                float pv = Ps[(nc * 8 + h) * 17 + row];
                float xv = Xs[j * 17 + row];
                rsum[e >> 1] = fmaf(pv * xv, acc[nt][e], rsum[e >> 1]);
            }
        #pragma unroll
        for (int i = 0; i < 2; i++) {
            rsum[i] += __shfl_xor_sync(0xFFFFFFFFu, rsum[i], 1);
            rsum[i] += __shfl_xor_sync(0xFFFFFFFFu, rsum[i], 2);
        }
        if ((lane & 3) == 0) {
            float* red = reinterpret_cast<float*>(smem + OFF_RED);
            red[wid * 16 + r]     = rsum[0];
            red[wid * 16 + r + 8] = rsum[1];
        }
    }
    __syncthreads();

    // ---- Final: sum 8 n-chunk warps per row, normalize, store ----
    if (tid < MTILE) {
        const float* red = reinterpret_cast<const float*>(smem + OFF_RED);
        float num = 0.0f;
        #pragma unroll
        for (int w = 0; w < 8; w++)
            num += red[w * 16 + tid];
        out[b0 + tid] = num * Rd[tid];
    }

    // ---- Counter reset (last block through restores g_prod/g_done = 0) ----
    if (tid == 0) {
        int d = atomicAdd(&g_done, 1);
        if (d == NBLOCKS - 1) {
            atomicExch(&g_prod, 0);
            atomicExch(&g_done, 0);
        }
    }
}

extern "C" void kernel_launch(void* const* d_in, const int* in_sizes, int n_in,
                              void* d_out, int out_size) {
    const float* x     = (const float*)d_in[0];
    const float* a     = (const float*)d_in[1];
    const float* b     = (const float*)d_in[2];
    const float* c     = (const float*)d_in[3];
    const float* coeff = (const float*)d_in[4];
    // d_in[5] = mf_indices: full itertools.product enumeration; digit decode analytic.
    float* out = (float*)d_out;

    anfis_fused_kernel<<<NBLOCKS, NTHREADS, SMEM_BYTES>>>(x, a, b, c, coeff, out);
}

// round 17
// speedup vs baseline: 1.0030x; 1.0030x over previous
#include <cuda_runtime.h>
#include <cstdint>

#define BATCH    4096
#define MTILE    16
#define NBLOCKS  (BATCH / MTILE)   // 256
#define NTHREADS 256               // 8 warps = 8 n-chunks of 56 cols

// smem byte offsets
#define OFF_QS   0                          // 16 rows x 68 f32 (A tile, raw fp32)
#define OFF_P    4352                       // 64 x stride17 f32
#define OFF_XP   (OFF_P + 64 * 17 * 4)      // 7 x stride17 f32
#define OFF_RD   (OFF_XP + 7 * 17 * 4)      // 16 f32
#define OFF_RED  (OFF_RD + 64)              // 8 warps x 16 rows f32
#define OFF_MSM  (OFF_RED + 8 * 16 * 4)     // 24 x 16 f32
#define OFF_SS   (OFF_MSM + 24 * 16 * 4)    // 6 x 16 f32
#define SMEM_BYTES (OFF_SS + 6 * 16 * 4 + 16)

// m16n8k8 tf32 MMA (sm_80+ baseline PTX, no 'a' features)
static __device__ __forceinline__ void mma1688(float* d, const uint32_t* a,
                                               uint32_t b0, uint32_t b1) {
    asm("mma.sync.aligned.m16n8k8.row.col.f32.tf32.tf32.f32 "
        "{%0,%1,%2,%3}, {%4,%5,%6,%7}, {%8,%9}, {%0,%1,%2,%3};"
        : "+f"(d[0]), "+f"(d[1]), "+f"(d[2]), "+f"(d[3])
        : "r"(a[0]), "r"(a[1]), "r"(a[2]), "r"(a[3]), "r"(b0), "r"(b1));
}
// 3xtf32 split: hi = v with mantissa bits [12:0] cleared (exactly tf32);
// lo = v - hi (exact in fp32). hi*hi + hi*lo + lo*hi ~ 1e-7 error.
static __device__ __forceinline__ uint32_t tf32hi(float v) {
    return __float_as_uint(v) & 0xFFFFE000u;
}
static __device__ __forceinline__ uint32_t tf32lo(float v, uint32_t h) {
    return __float_as_uint(v - __uint_as_float(h));
}

__global__ void __launch_bounds__(NTHREADS, 2) anfis_tf32_kernel(
    const float* __restrict__ x, const float* __restrict__ a,
    const float* __restrict__ b, const float* __restrict__ c,
    const float* __restrict__ coeff, float* __restrict__ out)
{
    extern __shared__ char smem[];
    float* Qs  = reinterpret_cast<float*>(smem + OFF_QS);   // [row][68]
    float* Ps  = reinterpret_cast<float*>(smem + OFF_P);    // [h][17]
    float* Xs  = reinterpret_cast<float*>(smem + OFF_XP);   // [j][17]
    float* Rd  = reinterpret_cast<float*>(smem + OFF_RD);
    float* Msm = reinterpret_cast<float*>(smem + OFF_MSM);  // [(i*4+k)*16 + bl]
    float* Ss  = reinterpret_cast<float*>(smem + OFF_SS);   // [i*16 + bl]

    const int tid  = threadIdx.x;
    const int lane = tid & 31;
    const int wid  = tid >> 5;
    const int b0   = blockIdx.x * MTILE;

    // ---- Phase A: memberships, (b,i) task per thread (96 threads) ----
    if (tid < 96) {
        const int bl = tid & 15;
        const int i  = tid >> 4;       // 0..5
        float xi = __ldg(&x[(b0 + bl) * 6 + i]);
        Xs[i * 17 + bl] = xi;
        float s = 0.0f;
        #pragma unroll
        for (int k = 0; k < 4; k++) {
            float av = __ldg(&a[i * 4 + k]);
            float bv = __ldg(&b[i * 4 + k]);
            float cv = __ldg(&c[i * 4 + k]);
            float d  = __fdividef(xi - cv, av);
            float d2 = d * d;
            float db = (bv == 2.0f) ? (d2 * d2) : __powf(d2, bv);
            float mv = __fdividef(1.0f, 1.0f + db);
            Msm[(i * 4 + k) * 16 + bl] = mv;
            s += mv;
        }
        Ss[i * 16 + bl] = s;
    }
    __syncthreads();

    // ---- Phase B: den, P table, raw-fp32 A tile — all 256 threads ----
    if (tid < 16) {
        float den = Ss[tid] * Ss[16 + tid] * Ss[32 + tid]
                  * Ss[48 + tid] * Ss[64 + tid] * Ss[80 + tid];
        Rd[tid] = __fdividef(1.0f, fmaxf(den, 1e-12f));
        Xs[6 * 17 + tid] = 1.0f;
    }
    // P table: 1024 entries (64 h x 16 rows), 4 per thread
    #pragma unroll
    for (int q = 0; q < 4; q++) {
        const int e  = tid + q * 256;
        const int h  = e >> 4;
        const int bl = e & 15;
        Ps[h * 17 + bl] = Msm[(0 + ((h >> 4) & 3)) * 16 + bl]
                        * Msm[(4 + ((h >> 2) & 3)) * 16 + bl]
                        * Msm[(8 + (h & 3)) * 16 + bl];
    }
    // A tile: Q[row][l] fp32, stride 68 (conflict-free fragment loads)
    #pragma unroll
    for (int q = 0; q < 4; q++) {
        const int u   = tid + q * 256;      // 1024 tasks
        const int row = u & 15;
        const int l   = u >> 4;             // 0..63
        float qv = Msm[(12 + ((l >> 4) & 3)) * 16 + row]
                 * Msm[(16 + ((l >> 2) & 3)) * 16 + row]
                 * Msm[(20 + (l & 3)) * 16 + row];
        Qs[row * 68 + l] = qv;
    }
    __syncthreads();

    // ---- TF32 mainloop: warp = 56-col chunk; B raw from coeff via L2 ----
    const int nc = wid;
    const int g  = lane >> 2;      // 0..7
    const int t  = lane & 3;       // 0..3

    // per-nt float offsets into coeff: B[k][n] = coeff[h*448 + k*7 + j],
    // n = nc*56 + nt*8 + g -> (h, j); k = ks*8 + t (b0), +4 (b1)
    int off[7];
    #pragma unroll
    for (int nt = 0; nt < 7; nt++) {
        int n = nc * 56 + nt * 8 + g;
        int h = n / 7;
        int j = n - h * 7;
        off[nt] = h * 448 + j + t * 7;
    }

    float acc[7][4];
    #pragma unroll
    for (int nt = 0; nt < 7; nt++)
        #pragma unroll
        for (int e = 0; e < 4; e++) acc[nt][e] = 0.0f;

    float braw[2][14];
    #pragma unroll
    for (int nt = 0; nt < 7; nt++) {
        braw[0][2 * nt]     = __ldg(coeff + off[nt]);
        braw[0][2 * nt + 1] = __ldg(coeff + off[nt] + 28);
    }

    #pragma unroll
    for (int ks = 0; ks < 8; ks++) {
        const int cur = ks & 1;
        if (ks < 7) {
            #pragma unroll
            for (int nt = 0; nt < 7; nt++) {
                braw[cur ^ 1][2 * nt]     = __ldg(coeff + off[nt] + (ks + 1) * 56);
                braw[cur ^ 1][2 * nt + 1] = __ldg(coeff + off[nt] + (ks + 1) * 56 + 28);
            }
        }
        // A fragment (rows g, g+8; k = ks*8 + t, +4), split hi/lo
        float a0 = Qs[g * 68 + ks * 8 + t];
        float a1 = Qs[(g + 8) * 68 + ks * 8 + t];
        float a2 = Qs[g * 68 + ks * 8 + t + 4];
        float a3 = Qs[(g + 8) * 68 + ks * 8 + t + 4];
        uint32_t ahi[4], alo[4];
        ahi[0] = tf32hi(a0); alo[0] = tf32lo(a0, ahi[0]);
        ahi[1] = tf32hi(a1); alo[1] = tf32lo(a1, ahi[1]);
        ahi[2] = tf32hi(a2); alo[2] = tf32lo(a2, ahi[2]);
        ahi[3] = tf32hi(a3); alo[3] = tf32lo(a3, ahi[3]);

        #pragma unroll
        for (int nt = 0; nt < 7; nt++) {
            float v0 = braw[cur][2 * nt];
            float v1 = braw[cur][2 * nt + 1];
            uint32_t bh0 = tf32hi(v0), bl0 = tf32lo(v0, bh0);
            uint32_t bh1 = tf32hi(v1), bl1 = tf32lo(v1, bh1);
            mma1688(acc[nt], ahi, bh0, bh1);   // hi*hi
            mma1688(acc[nt], ahi, bl0, bl1);   // hi*lo
            mma1688(acc[nt], alo, bh0, bh1);   // lo*hi
        }
    }

    // ---- Epilogue: fold P * x_plus, reduce quads, stash per-warp rows ----
    {
        float rsum[2] = {0.f, 0.f};
        #pragma unroll
        for (int nt = 0; nt < 7; nt++)
            #pragma unroll
            for (int e = 0; e < 4; e++) {
                const int row = g + (e >> 1) * 8;     // 0..15
                const int u   = nt * 8 + 2 * t + (e & 1);
                const int h   = u / 7;
                const int j   = u - h * 7;
                float pv = Ps[(nc * 8 + h) * 17 + row];
                float xv = Xs[j * 17 + row];
                rsum[e >> 1] = fmaf(pv * xv, acc[nt][e], rsum[e >> 1]);
            }
        #pragma unroll
        for (int i = 0; i < 2; i++) {
            rsum[i] += __shfl_xor_sync(0xFFFFFFFFu, rsum[i], 1);
            rsum[i] += __shfl_xor_sync(0xFFFFFFFFu, rsum[i], 2);
        }
        if (t == 0) {
            float* red = reinterpret_cast<float*>(smem + OFF_RED);
            red[wid * 16 + g]     = rsum[0];
            red[wid * 16 + g + 8] = rsum[1];
        }
    }
    __syncthreads();

    // ---- Final: sum 8 n-chunk warps per row, normalize, store ----
    if (tid < MTILE) {
        const float* red = reinterpret_cast<const float*>(smem + OFF_RED);
        float num = 0.0f;
        #pragma unroll
        for (int w = 0; w < 8; w++)
            num += red[w * 16 + tid];
        out[b0 + tid] = num * Rd[tid];
    }
}

extern "C" void kernel_launch(void* const* d_in, const int* in_sizes, int n_in,
                              void* d_out, int out_size) {
    const float* x     = (const float*)d_in[0];
    const float* a     = (const float*)d_in[1];
    const float* b     = (const float*)d_in[2];
    const float* c     = (const float*)d_in[3];
    const float* coeff = (const float*)d_in[4];
    // d_in[5] = mf_indices: full itertools.product enumeration; digit decode analytic.
    float* out = (float*)d_out;

    anfis_tf32_kernel<<<NBLOCKS, NTHREADS, SMEM_BYTES>>>(x, a, b, c, coeff, out);
}